// round 1
// baseline (speedup 1.0000x reference)
#include <cuda_runtime.h>
#include <cuda_bf16.h>
#include <math.h>

#define N_IMG 8
#define C_CH  64
#define HW    128
#define PLANE (HW*HW)          // 16384
#define NPLANES (N_IMG*C_CH)   // 512
#define KK 9
#define SMEM_STRIDE 132
#define SMEM_FLOATS (130*SMEM_STRIDE)     // 17160 floats = 68640 B

// scratch (device globals — no allocation allowed)
__device__ float g_gap[NPLANES];          // (n, C) global-avg-pool
__device__ float g_w[NPLANES * KK];       // (n, C, 9) softmax weights

// ---------------------------------------------------------------------------
// Kernel 1: global average pool per (n,c) plane
// ---------------------------------------------------------------------------
__global__ void gap_kernel(const float* __restrict__ x) {
    int plane = blockIdx.x;
    const float4* p = reinterpret_cast<const float4*>(x + (size_t)plane * PLANE);
    float s = 0.f;
    for (int i = threadIdx.x; i < PLANE / 4; i += 256) {
        float4 v = p[i];
        s += v.x + v.y + v.z + v.w;
    }
    #pragma unroll
    for (int o = 16; o; o >>= 1) s += __shfl_down_sync(0xffffffffu, s, o);
    __shared__ float ws[8];
    if ((threadIdx.x & 31) == 0) ws[threadIdx.x >> 5] = s;
    __syncthreads();
    if (threadIdx.x < 8) {
        float v = ws[threadIdx.x];
        #pragma unroll
        for (int o = 4; o; o >>= 1) v += __shfl_down_sync(0xffu, v, o);
        if (threadIdx.x == 0) g_gap[plane] = v * (1.f / (float)PLANE);
    }
}

// ---------------------------------------------------------------------------
// Kernel 2: f = gap @ conv_w.T ; BN(eval) ; softmax over 9 taps
// grid = N_IMG, block = C_CH threads; each thread owns one channel's 9 taps
// ---------------------------------------------------------------------------
__global__ void weight_kernel(const float* __restrict__ conv_w,
                              const float* __restrict__ gamma,
                              const float* __restrict__ beta,
                              const float* __restrict__ mean,
                              const float* __restrict__ var) {
    __shared__ float gs[C_CH];
    int n = blockIdx.x;
    int c = threadIdx.x;
    gs[c] = g_gap[n * C_CH + c];
    __syncthreads();

    float vals[KK];
    #pragma unroll
    for (int k = 0; k < KK; k++) {
        int row = c * KK + k;                    // output channel index in [0,576)
        const float* wr = conv_w + (size_t)row * C_CH;
        float acc = 0.f;
        #pragma unroll 16
        for (int cc = 0; cc < C_CH; cc++) acc += gs[cc] * wr[cc];
        float inv = rsqrtf(var[row] + 1e-5f);
        vals[k] = (acc - mean[row]) * (gamma[row] * inv) + beta[row];
    }
    // softmax over the 9 taps (registers)
    float mx = vals[0];
    #pragma unroll
    for (int k = 1; k < KK; k++) mx = fmaxf(mx, vals[k]);
    float sum = 0.f;
    #pragma unroll
    for (int k = 0; k < KK; k++) { vals[k] = expf(vals[k] - mx); sum += vals[k]; }
    float is = 1.f / sum;
    #pragma unroll
    for (int k = 0; k < KK; k++) g_w[(n * C_CH + c) * KK + k] = vals[k] * is;
}

// ---------------------------------------------------------------------------
// Kernel 3: reflect-pad + 9-tap weighted sum; writes out and x-out
// One CTA per (n,c) plane, plane staged in padded smem (130 x 132)
// ---------------------------------------------------------------------------
__global__ void conv_kernel(const float* __restrict__ x,
                            float* __restrict__ out,
                            float* __restrict__ diff) {
    extern __shared__ float sp[];  // [130][SMEM_STRIDE], logical xp at [0..129][0..129]
    int plane = blockIdx.x;
    const float4* x4 = reinterpret_cast<const float4*>(x + (size_t)plane * PLANE);

    // interior: x row r -> sp row r+1, x col j -> sp col j+1
    for (int i = threadIdx.x; i < PLANE / 4; i += 256) {
        int r = i >> 5;            // 32 float4 per row
        int cq = i & 31;
        float4 v = x4[i];
        float* d = &sp[(r + 1) * SMEM_STRIDE + 1 + cq * 4];
        d[0] = v.x; d[1] = v.y; d[2] = v.z; d[3] = v.w;
    }
    __syncthreads();
    // column halos (reflect): xp[.,0]=x[.,1]  xp[.,129]=x[.,126]
    for (int r = 1 + threadIdx.x; r <= 128; r += 256) {
        sp[r * SMEM_STRIDE + 0]   = sp[r * SMEM_STRIDE + 2];
        sp[r * SMEM_STRIDE + 129] = sp[r * SMEM_STRIDE + 127];
    }
    __syncthreads();
    // row halos incl. corners: xp[0,:]=xp[2,:]  xp[129,:]=xp[127,:]
    for (int j = threadIdx.x; j < 130; j += 256) {
        sp[0 * SMEM_STRIDE + j]   = sp[2 * SMEM_STRIDE + j];
        sp[129 * SMEM_STRIDE + j] = sp[127 * SMEM_STRIDE + j];
    }

    float w[KK];
    const float* wp = g_w + plane * KK;
    #pragma unroll
    for (int k = 0; k < KK; k++) w[k] = wp[k];
    __syncthreads();

    float4* out4  = reinterpret_cast<float4*>(out  + (size_t)plane * PLANE);
    float4* diff4 = reinterpret_cast<float4*>(diff + (size_t)plane * PLANE);

    for (int i = threadIdx.x; i < PLANE / 4; i += 256) {
        int r = i >> 5;
        int c0 = (i & 31) * 4;
        float res[4];
        #pragma unroll
        for (int l = 0; l < 4; l++) {
            float acc = 0.f;
            #pragma unroll
            for (int ki = 0; ki < 3; ki++) {
                const float* row = &sp[(r + ki) * SMEM_STRIDE + c0 + l];
                acc = fmaf(w[ki * 3 + 0], row[0], acc);
                acc = fmaf(w[ki * 3 + 1], row[1], acc);
                acc = fmaf(w[ki * 3 + 2], row[2], acc);
            }
            res[l] = acc;
        }
        const float* xr = &sp[(r + 1) * SMEM_STRIDE + c0 + 1];
        float4 o = make_float4(res[0], res[1], res[2], res[3]);
        float4 d = make_float4(xr[0] - res[0], xr[1] - res[1],
                               xr[2] - res[2], xr[3] - res[3]);
        out4[i]  = o;
        diff4[i] = d;
    }
}

// ---------------------------------------------------------------------------
extern "C" void kernel_launch(void* const* d_in, const int* in_sizes, int n_in,
                              void* d_out, int out_size) {
    const float* x      = (const float*)d_in[0];
    const float* conv_w = (const float*)d_in[1];
    const float* gamma  = (const float*)d_in[2];
    const float* beta   = (const float*)d_in[3];
    const float* mean   = (const float*)d_in[4];
    const float* var    = (const float*)d_in[5];

    float* out  = (float*)d_out;
    float* diff = out + (size_t)NPLANES * PLANE;

    static_assert(SMEM_FLOATS * 4 == 68640, "smem size");
    cudaFuncSetAttribute(conv_kernel, cudaFuncAttributeMaxDynamicSharedMemorySize,
                         SMEM_FLOATS * (int)sizeof(float));

    gap_kernel<<<NPLANES, 256>>>(x);
    weight_kernel<<<N_IMG, C_CH>>>(conv_w, gamma, beta, mean, var);
    conv_kernel<<<NPLANES, 256, SMEM_FLOATS * sizeof(float)>>>(x, out, diff);
}

// round 4
// speedup vs baseline: 2.3770x; 2.3770x over previous
#include <cuda_runtime.h>
#include <cuda_bf16.h>
#include <math.h>

#define N_IMG 8
#define C_CH  64
#define HW    128
#define PLANE (HW*HW)            // 16384
#define NPLANES (N_IMG*C_CH)     // 512
#define KK 9

// gap partial sums: 4 segments per plane
__device__ float g4[NPLANES * 4];

// ---------------------------------------------------------------------------
// Kernel 1: partial global-average-pool. 2048 CTAs, each sums a quarter plane.
// ---------------------------------------------------------------------------
__global__ void gap_kernel(const float* __restrict__ x) {
    int seg = blockIdx.x;                         // plane*4 + q
    const float4* p = reinterpret_cast<const float4*>(x) + (size_t)seg * 1024;
    float s = 0.f;
    #pragma unroll
    for (int k = 0; k < 4; k++) {
        float4 v = p[threadIdx.x + k * 256];
        s += (v.x + v.y) + (v.z + v.w);
    }
    #pragma unroll
    for (int o = 16; o; o >>= 1) s += __shfl_xor_sync(0xffffffffu, s, o);
    __shared__ float ws[8];
    if ((threadIdx.x & 31) == 0) ws[threadIdx.x >> 5] = s;
    __syncthreads();
    if (threadIdx.x == 0) {
        float v = ws[0] + ws[1] + ws[2] + ws[3] + ws[4] + ws[5] + ws[6] + ws[7];
        g4[seg] = v;
    }
}

// ---------------------------------------------------------------------------
// Kernel 2 (fused): per-CTA weight computation + reflect-pad 9-tap conv.
// One CTA per (plane, half): 64 output rows. Static smem 66x136 floats.
// Row layout: x col c -> idx 4+c ; left halo (x col 1) -> idx 3 ;
//             right halo (x col 126) -> idx 132. All float4 LDS aligned.
// ---------------------------------------------------------------------------
#define ST 136
#define SROWS 66

__global__ __launch_bounds__(256) void conv_kernel(
        const float* __restrict__ x,
        const float* __restrict__ conv_w,
        const float* __restrict__ gamma,
        const float* __restrict__ beta,
        const float* __restrict__ mean,
        const float* __restrict__ var,
        float* __restrict__ out,
        float* __restrict__ diff) {
    __shared__ float sp[SROWS * ST];     // 35904 B
    __shared__ float gs[C_CH];
    __shared__ float wsm[12];

    int tid   = threadIdx.x;
    int plane = blockIdx.x >> 1;
    int R0    = (blockIdx.x & 1) * 64;
    int n     = plane >> 6;
    int ch    = plane & 63;

    const float* xp = x + (size_t)plane * PLANE;
    const float4* x4 = reinterpret_cast<const float4*>(xp);

    // ---- stage 66 rows (with row reflection) into smem ----
    #pragma unroll
    for (int k = 0; k < 9; k++) {
        int i = tid + k * 256;
        if (i < SROWS * 32) {
            int s  = i >> 5;
            int cq = i & 31;
            int gr = R0 - 1 + s;
            gr = (gr < 0) ? 1 : (gr > 127 ? 126 : gr);   // reflect(-1)=1, reflect(128)=126
            float4 v = x4[gr * 32 + cq];
            float* d = &sp[s * ST + 4 + cq * 4];
            d[0] = v.x; d[1] = v.y; d[2] = v.z; d[3] = v.w;
        }
    }
    // column halos straight from global
    if (tid < SROWS) {
        int gr = R0 - 1 + tid;
        gr = (gr < 0) ? 1 : (gr > 127 ? 126 : gr);
        sp[tid * ST + 3]   = xp[gr * HW + 1];     // xp[.,0]   = x[.,1]
        sp[tid * ST + 132] = xp[gr * HW + 126];   // xp[.,129] = x[.,126]
    }
    // GAP combine for this image's 64 channels
    if (tid < C_CH) {
        const float* g = &g4[(n * C_CH + tid) * 4];
        gs[tid] = (g[0] + g[1] + g[2] + g[3]) * (1.f / (float)PLANE);
    }
    __syncthreads();

    // ---- warp 0: 9 dot products -> BN -> softmax -> wsm ----
    if (tid < 32) {
        float val = -1e30f;
        if (tid < KK) {
            int row = ch * KK + tid;
            const float* wr = conv_w + (size_t)row * C_CH;
            float acc = 0.f;
            #pragma unroll
            for (int cc = 0; cc < C_CH; cc++) acc += gs[cc] * wr[cc];
            float inv = rsqrtf(var[row] + 1e-5f);
            val = (acc - mean[row]) * (gamma[row] * inv) + beta[row];
        }
        float m = val;
        #pragma unroll
        for (int o = 16; o; o >>= 1) m = fmaxf(m, __shfl_xor_sync(0xffffffffu, m, o));
        float e = (tid < KK) ? expf(val - m) : 0.f;
        float ssum = e;
        #pragma unroll
        for (int o = 16; o; o >>= 1) ssum += __shfl_xor_sync(0xffffffffu, ssum, o);
        if (tid < KK) wsm[tid] = e / ssum;
    }
    __syncthreads();

    float w[KK];
    #pragma unroll
    for (int k = 0; k < KK; k++) w[k] = wsm[k];

    float4* out4  = reinterpret_cast<float4*>(out  + (size_t)plane * PLANE + (size_t)R0 * HW);
    float4* diff4 = reinterpret_cast<float4*>(diff + (size_t)plane * PLANE + (size_t)R0 * HW);

    // ---- compute: 8 float4 outputs per thread ----
    #pragma unroll
    for (int k = 0; k < 8; k++) {
        int i  = tid + k * 256;
        int r  = i >> 5;           // output row within half (0..63)
        int cq = i & 31;
        int c0 = cq * 4;

        float acc0 = 0.f, acc1 = 0.f, acc2 = 0.f, acc3 = 0.f;
        float4 Mmid;
        #pragma unroll
        for (int ki = 0; ki < 3; ki++) {
            const float* rb = &sp[(r + ki) * ST];
            float4 L = *reinterpret_cast<const float4*>(rb + c0);       // x cols c0-4..c0-1 (only .w used)
            float4 M = *reinterpret_cast<const float4*>(rb + 4 + c0);   // x cols c0..c0+3
            float4 R = *reinterpret_cast<const float4*>(rb + 8 + c0);   // x cols c0+4..c0+7 (only .x used)
            float w0 = w[ki * 3 + 0], w1 = w[ki * 3 + 1], w2 = w[ki * 3 + 2];
            // out col c taps: xp cols c..c+2 = x cols c-1, c, c+1
            acc0 = fmaf(w0, L.w, fmaf(w1, M.x, fmaf(w2, M.y, acc0)));
            acc1 = fmaf(w0, M.x, fmaf(w1, M.y, fmaf(w2, M.z, acc1)));
            acc2 = fmaf(w0, M.y, fmaf(w1, M.z, fmaf(w2, M.w, acc2)));
            acc3 = fmaf(w0, M.z, fmaf(w1, M.w, fmaf(w2, R.x, acc3)));
            if (ki == 1) Mmid = M;
        }
        int oi = r * 32 + cq;
        out4[oi]  = make_float4(acc0, acc1, acc2, acc3);
        diff4[oi] = make_float4(Mmid.x - acc0, Mmid.y - acc1,
                                Mmid.z - acc2, Mmid.w - acc3);
    }
}

// ---------------------------------------------------------------------------
extern "C" void kernel_launch(void* const* d_in, const int* in_sizes, int n_in,
                              void* d_out, int out_size) {
    const float* x      = (const float*)d_in[0];
    const float* conv_w = (const float*)d_in[1];
    const float* gamma  = (const float*)d_in[2];
    const float* beta   = (const float*)d_in[3];
    const float* mean   = (const float*)d_in[4];
    const float* var    = (const float*)d_in[5];

    float* out  = (float*)d_out;
    float* diff = out + (size_t)NPLANES * PLANE;

    gap_kernel<<<NPLANES * 4, 256>>>(x);
    conv_kernel<<<NPLANES * 2, 256>>>(x, conv_w, gamma, beta, mean, var, out, diff);
}

// round 11
// speedup vs baseline: 2.7358x; 1.1509x over previous
#include <cuda_runtime.h>
#include <cuda_bf16.h>
#include <math.h>

#define N_IMG 8
#define C_CH  64
#define HW    128
#define PLANE (HW*HW)            // 16384
#define NPLANES (N_IMG*C_CH)     // 512
#define KK 9
#define ST 136
#define SROWS 66

// gap partial sums: 4 segments per plane
__device__ float g4[NPLANES * 4];

// ---------------------------------------------------------------------------
// Kernel 1: partial global-average-pool. 2048 CTAs, each sums a quarter plane.
// ---------------------------------------------------------------------------
__global__ void gap_kernel(const float* __restrict__ x) {
    int seg = blockIdx.x;                         // plane*4 + q
    const float4* p = reinterpret_cast<const float4*>(x) + (size_t)seg * 1024;
    float s = 0.f;
    #pragma unroll
    for (int k = 0; k < 4; k++) {
        float4 v = p[threadIdx.x + k * 256];
        s += (v.x + v.y) + (v.z + v.w);
    }
    #pragma unroll
    for (int o = 16; o; o >>= 1) s += __shfl_xor_sync(0xffffffffu, s, o);
    __shared__ float ws[8];
    if ((threadIdx.x & 31) == 0) ws[threadIdx.x >> 5] = s;
    __syncthreads();
    if (threadIdx.x == 0) {
        float v = ws[0] + ws[1] + ws[2] + ws[3] + ws[4] + ws[5] + ws[6] + ws[7];
        g4[seg] = v;
    }
}

// ---------------------------------------------------------------------------
// Kernel 2: per-CTA weight computation + reflect-pad 9-tap sliding-window conv
// One CTA per (plane, half): 64 output rows. Static smem 66x136 floats.
// Row layout: x col c -> idx 4+c ; halos at idx 3 / 132; float4 LDS aligned.
// ---------------------------------------------------------------------------
__global__ __launch_bounds__(256) void conv_kernel(
        const float* __restrict__ x,
        const float* __restrict__ conv_w,
        const float* __restrict__ gamma,
        const float* __restrict__ beta,
        const float* __restrict__ mean,
        const float* __restrict__ var,
        float* __restrict__ out,
        float* __restrict__ diff) {
    __shared__ float sp[SROWS * ST];     // 35904 B
    __shared__ float gs[C_CH];
    __shared__ float wsm[12];

    int tid   = threadIdx.x;
    int plane = blockIdx.x >> 1;
    int R0    = (blockIdx.x & 1) * 64;
    int n     = plane >> 6;
    int ch    = plane & 63;

    const float* xp = x + (size_t)plane * PLANE;
    const float4* x4 = reinterpret_cast<const float4*>(xp);

    // ---- stage 66 rows (with row reflection) into smem ----
    #pragma unroll
    for (int k = 0; k < 9; k++) {
        int i = tid + k * 256;
        if (i < SROWS * 32) {
            int s  = i >> 5;
            int cq = i & 31;
            int gr = R0 - 1 + s;
            gr = (gr < 0) ? 1 : (gr > 127 ? 126 : gr);   // reflect(-1)=1, reflect(128)=126
            float4 v = x4[gr * 32 + cq];
            float* d = &sp[s * ST + 4 + cq * 4];
            d[0] = v.x; d[1] = v.y; d[2] = v.z; d[3] = v.w;
        }
    }
    // column halos straight from global
    if (tid < SROWS) {
        int gr = R0 - 1 + tid;
        gr = (gr < 0) ? 1 : (gr > 127 ? 126 : gr);
        sp[tid * ST + 3]   = xp[gr * HW + 1];     // xp[.,0]   = x[.,1]
        sp[tid * ST + 132] = xp[gr * HW + 126];   // xp[.,129] = x[.,126]
    }
    // GAP combine for this image's 64 channels
    if (tid < C_CH) {
        const float* g = &g4[(n * C_CH + tid) * 4];
        gs[tid] = (g[0] + g[1] + g[2] + g[3]) * (1.f / (float)PLANE);
    }
    __syncthreads();

    // ---- warp 0: 9 dot products -> BN -> softmax -> wsm ----
    if (tid < 32) {
        float val = -1e30f;
        if (tid < KK) {
            int row = ch * KK + tid;
            const float* wr = conv_w + (size_t)row * C_CH;
            float acc = 0.f;
            #pragma unroll
            for (int cc = 0; cc < C_CH; cc++) acc += gs[cc] * wr[cc];
            float inv = rsqrtf(var[row] + 1e-5f);
            val = (acc - mean[row]) * (gamma[row] * inv) + beta[row];
        }
        float m = val;
        #pragma unroll
        for (int o = 16; o; o >>= 1) m = fmaxf(m, __shfl_xor_sync(0xffffffffu, m, o));
        float e = (tid < KK) ? expf(val - m) : 0.f;
        float ssum = e;
        #pragma unroll
        for (int o = 16; o; o >>= 1) ssum += __shfl_xor_sync(0xffffffffu, ssum, o);
        if (tid < KK) wsm[tid] = e / ssum;
    }
    __syncthreads();

    float w[KK];
    #pragma unroll
    for (int k = 0; k < KK; k++) w[k] = wsm[k];

    // ---- sliding-window conv: thread = (column quad cq, 8-row strip) ----
    int cq    = tid & 31;
    int strip = tid >> 5;
    int c0    = cq * 4;
    int sbase = strip * 8;                 // out rows sbase..sbase+7 (within half)

    float acc[8][4];
    #pragma unroll
    for (int r = 0; r < 8; r++) {
        acc[r][0] = 0.f; acc[r][1] = 0.f; acc[r][2] = 0.f; acc[r][3] = 0.f;
    }

    #pragma unroll
    for (int s = 0; s < 10; s++) {         // smem rows sbase+s (out row r uses rows r..r+2)
        const float* rb = &sp[(sbase + s) * ST];
        float4 L = *reinterpret_cast<const float4*>(rb + c0);
        float4 M = *reinterpret_cast<const float4*>(rb + 4 + c0);
        float4 R = *reinterpret_cast<const float4*>(rb + 8 + c0);
        float sm1[4] = {L.w, M.x, M.y, M.z};
        float s00[4] = {M.x, M.y, M.z, M.w};
        float sp1[4] = {M.y, M.z, M.w, R.x};
        #pragma unroll
        for (int ki = 0; ki < 3; ki++) {   // smem row s feeds out row s-ki with weight row ki
            int r = s - ki;
            if (r >= 0 && r < 8) {
                float w0 = w[ki * 3 + 0], w1 = w[ki * 3 + 1], w2 = w[ki * 3 + 2];
                #pragma unroll
                for (int l = 0; l < 4; l++)
                    acc[r][l] = fmaf(w0, sm1[l], fmaf(w1, s00[l], fmaf(w2, sp1[l], acc[r][l])));
            }
        }
    }

    float4* out4  = reinterpret_cast<float4*>(out  + (size_t)plane * PLANE + (size_t)R0 * HW);
    float4* diff4 = reinterpret_cast<float4*>(diff + (size_t)plane * PLANE + (size_t)R0 * HW);

    #pragma unroll
    for (int r = 0; r < 8; r++) {
        const float* rb = &sp[(sbase + r + 1) * ST];
        float4 M = *reinterpret_cast<const float4*>(rb + 4 + c0);   // x center row
        int oi = (sbase + r) * 32 + cq;
        out4[oi]  = make_float4(acc[r][0], acc[r][1], acc[r][2], acc[r][3]);
        diff4[oi] = make_float4(M.x - acc[r][0], M.y - acc[r][1],
                                M.z - acc[r][2], M.w - acc[r][3]);
    }
}

// ---------------------------------------------------------------------------
extern "C" void kernel_launch(void* const* d_in, const int* in_sizes, int n_in,
                              void* d_out, int out_size) {
    const float* x      = (const float*)d_in[0];
    const float* conv_w = (const float*)d_in[1];
    const float* gamma  = (const float*)d_in[2];
    const float* beta   = (const float*)d_in[3];
    const float* mean   = (const float*)d_in[4];
    const float* var    = (const float*)d_in[5];

    float* out  = (float*)d_out;
    float* diff = out + (size_t)NPLANES * PLANE;

    gap_kernel<<<NPLANES * 4, 256>>>(x);
    conv_kernel<<<NPLANES * 2, 256>>>(x, conv_w, gamma, beta, mean, var, out, diff);
}

// round 12
// speedup vs baseline: 2.9592x; 1.0816x over previous
#include <cuda_runtime.h>
#include <cuda_bf16.h>
#include <math.h>

#define N_IMG 8
#define C_CH  64
#define HW    128
#define PLANE (HW*HW)            // 16384
#define NPLANES (N_IMG*C_CH)     // 512
#define KK 9

// gap partial sums: 4 segments per plane
__device__ float g4[NPLANES * 4];

// ---------------------------------------------------------------------------
// Kernel 1: partial global-average-pool. 2048 CTAs, each sums a quarter plane.
// ---------------------------------------------------------------------------
__global__ void gap_kernel(const float* __restrict__ x) {
    int seg = blockIdx.x;                         // plane*4 + q
    const float4* p = reinterpret_cast<const float4*>(x) + (size_t)seg * 1024;
    float s = 0.f;
    #pragma unroll
    for (int k = 0; k < 4; k++) {
        float4 v = p[threadIdx.x + k * 256];
        s += (v.x + v.y) + (v.z + v.w);
    }
    #pragma unroll
    for (int o = 16; o; o >>= 1) s += __shfl_xor_sync(0xffffffffu, s, o);
    __shared__ float ws[8];
    if ((threadIdx.x & 31) == 0) ws[threadIdx.x >> 5] = s;
    __syncthreads();
    if (threadIdx.x == 0) {
        float v = ws[0] + ws[1] + ws[2] + ws[3] + ws[4] + ws[5] + ws[6] + ws[7];
        g4[seg] = v;
    }
}

// ---------------------------------------------------------------------------
// Kernel 2: smem-free warp-shuffle sliding-window conv.
// CTA = (plane, half). Warp = full 128-col row; lane owns 4 cols.
// Each input row: ONE float4 LDG, column neighbors via shuffles,
// contributes to out rows t-1,t,t+1 via 3 rotating register slots.
// ---------------------------------------------------------------------------
__global__ __launch_bounds__(256) void conv_kernel(
        const float* __restrict__ x,
        const float* __restrict__ conv_w,
        const float* __restrict__ gamma,
        const float* __restrict__ beta,
        const float* __restrict__ mean,
        const float* __restrict__ var,
        float* __restrict__ out,
        float* __restrict__ diff) {
    __shared__ float gs[C_CH];
    __shared__ float wsm[12];

    int tid   = threadIdx.x;
    int lane  = tid & 31;
    int wrp   = tid >> 5;
    int plane = blockIdx.x >> 1;
    int R0    = (blockIdx.x & 1) * 64;
    int n     = plane >> 6;
    int ch    = plane & 63;

    // GAP combine for this image's 64 channels
    if (tid < C_CH) {
        const float* g = &g4[(n * C_CH + tid) * 4];
        gs[tid] = (g[0] + g[1] + g[2] + g[3]) * (1.f / (float)PLANE);
    }
    __syncthreads();

    // warp 0: 9 dot products -> BN -> softmax -> wsm
    if (tid < 32) {
        float val = -1e30f;
        if (tid < KK) {
            int row = ch * KK + tid;
            const float* wr = conv_w + (size_t)row * C_CH;
            float acc = 0.f;
            #pragma unroll
            for (int cc = 0; cc < C_CH; cc++) acc += gs[cc] * wr[cc];
            float inv = rsqrtf(var[row] + 1e-5f);
            val = (acc - mean[row]) * (gamma[row] * inv) + beta[row];
        }
        float m = val;
        #pragma unroll
        for (int o = 16; o; o >>= 1) m = fmaxf(m, __shfl_xor_sync(0xffffffffu, m, o));
        float e = (tid < KK) ? expf(val - m) : 0.f;
        float ssum = e;
        #pragma unroll
        for (int o = 16; o; o >>= 1) ssum += __shfl_xor_sync(0xffffffffu, ssum, o);
        if (tid < KK) wsm[tid] = e / ssum;
    }
    __syncthreads();

    float wt[KK];
    #pragma unroll
    for (int k = 0; k < KK; k++) wt[k] = wsm[k];

    const float4* x4 = reinterpret_cast<const float4*>(x + (size_t)plane * PLANE);
    float4* out4  = reinterpret_cast<float4*>(out  + (size_t)plane * PLANE);
    float4* diff4 = reinterpret_cast<float4*>(diff + (size_t)plane * PLANE);

    int R = R0 + wrp * 8;                 // this warp's 8 output rows: R..R+7

    float acc[3][4];                       // rotating slots, slot = rr % 3
    float ctr[3][4];                       // saved center-row x values (for diff)

    #pragma unroll
    for (int s = 0; s < 10; s++) {         // input row t = R-1+s
        int t  = R - 1 + s;
        int gr = (t < 0) ? 1 : (t > 127 ? 126 : t);     // reflect
        float4 v = x4[gr * 32 + lane];
        float lft = __shfl_up_sync(0xffffffffu, v.w, 1);
        float rgt = __shfl_down_sync(0xffffffffu, v.x, 1);
        if (lane == 0)  lft = v.y;         // xp col 0 = x col 1
        if (lane == 31) rgt = v.z;         // xp col 129 = x col 126
        float sm1[4] = {lft, v.x, v.y, v.z};
        float s00[4] = {v.x, v.y, v.z, v.w};
        float sp1[4] = {v.y, v.z, v.w, rgt};

        // init slot for out row rr = s (weight row 0: taps = input row r-1)
        if (s < 8) {
            int sl = s % 3;
            #pragma unroll
            for (int l = 0; l < 4; l++)
                acc[sl][l] = fmaf(wt[0], sm1[l], fmaf(wt[1], s00[l], wt[2] * sp1[l]));
        }
        // center for out row rr = s-1 (weight row 1); save x for diff
        if (s >= 1 && s <= 8) {
            int sl = (s - 1) % 3;
            #pragma unroll
            for (int l = 0; l < 4; l++) {
                acc[sl][l] = fmaf(wt[3], sm1[l], fmaf(wt[4], s00[l],
                                  fmaf(wt[5], sp1[l], acc[sl][l])));
                ctr[sl][l] = s00[l];
            }
        }
        // final for out row rr = s-2 (weight row 2), then emit
        if (s >= 2) {
            int sl = (s - 2) % 3;
            #pragma unroll
            for (int l = 0; l < 4; l++)
                acc[sl][l] = fmaf(wt[6], sm1[l], fmaf(wt[7], s00[l],
                                  fmaf(wt[8], sp1[l], acc[sl][l])));
            int oi = (R + s - 2) * 32 + lane;
            out4[oi]  = make_float4(acc[sl][0], acc[sl][1], acc[sl][2], acc[sl][3]);
            diff4[oi] = make_float4(ctr[sl][0] - acc[sl][0], ctr[sl][1] - acc[sl][1],
                                    ctr[sl][2] - acc[sl][2], ctr[sl][3] - acc[sl][3]);
        }
    }
}

// ---------------------------------------------------------------------------
extern "C" void kernel_launch(void* const* d_in, const int* in_sizes, int n_in,
                              void* d_out, int out_size) {
    const float* x      = (const float*)d_in[0];
    const float* conv_w = (const float*)d_in[1];
    const float* gamma  = (const float*)d_in[2];
    const float* beta   = (const float*)d_in[3];
    const float* mean   = (const float*)d_in[4];
    const float* var    = (const float*)d_in[5];

    float* out  = (float*)d_out;
    float* diff = out + (size_t)NPLANES * PLANE;

    gap_kernel<<<NPLANES * 4, 256>>>(x);
    conv_kernel<<<NPLANES * 2, 256>>>(x, conv_w, gamma, beta, mean, var, out, diff);
}

// round 13
// speedup vs baseline: 3.1912x; 1.0784x over previous
#include <cuda_runtime.h>
#include <cuda_bf16.h>
#include <math.h>

#define N_IMG 8
#define C_CH  64
#define HW    128
#define PLANE (HW*HW)            // 16384
#define NPLANES (N_IMG*C_CH)     // 512
#define KK 9

// gap partial sums: 4 segments per plane
__device__ float g4[NPLANES * 4];

// ---------------------------------------------------------------------------
// Kernel 1: partial global-average-pool. 2048 CTAs, each sums a quarter plane.
// ---------------------------------------------------------------------------
__global__ void gap_kernel(const float* __restrict__ x) {
    int seg = blockIdx.x;                         // plane*4 + q
    const float4* p = reinterpret_cast<const float4*>(x) + (size_t)seg * 1024;
    float s = 0.f;
    #pragma unroll
    for (int k = 0; k < 4; k++) {
        float4 v = p[threadIdx.x + k * 256];
        s += (v.x + v.y) + (v.z + v.w);
    }
    #pragma unroll
    for (int o = 16; o; o >>= 1) s += __shfl_xor_sync(0xffffffffu, s, o);
    __shared__ float ws[8];
    if ((threadIdx.x & 31) == 0) ws[threadIdx.x >> 5] = s;
    __syncthreads();
    if (threadIdx.x == 0) {
        float v = ws[0] + ws[1] + ws[2] + ws[3] + ws[4] + ws[5] + ws[6] + ws[7];
        g4[seg] = v;
    }
}

// ---------------------------------------------------------------------------
// Kernel 2: smem-free warp-shuffle sliding-window conv, single-wave occupancy.
// CTA = (plane, half). Warp = full 128-col row; lane owns 4 cols.
// Weight prologue parallelized across all 8 warps (warp-reduction dots).
// ---------------------------------------------------------------------------
__global__ __launch_bounds__(256, 8) void conv_kernel(
        const float* __restrict__ x,
        const float* __restrict__ conv_w,
        const float* __restrict__ gamma,
        const float* __restrict__ beta,
        const float* __restrict__ mean,
        const float* __restrict__ var,
        float* __restrict__ out,
        float* __restrict__ diff) {
    __shared__ float gs[C_CH];
    __shared__ float raw[12];
    __shared__ float wsm[12];

    int tid   = threadIdx.x;
    int lane  = tid & 31;
    int wrp   = tid >> 5;
    int plane = blockIdx.x >> 1;
    int R0    = (blockIdx.x & 1) * 64;
    int n     = plane >> 6;
    int ch    = plane & 63;

    // GAP combine for this image's 64 channels
    if (tid < C_CH) {
        const float* g = &g4[(n * C_CH + tid) * 4];
        gs[tid] = (g[0] + g[1] + g[2] + g[3]) * (1.f / (float)PLANE);
    }
    __syncthreads();

    // ---- weight dots distributed over warps: warp w -> rows w, w+8 ----
    for (int row = wrp; row < KK; row += 8) {
        int grow = ch * KK + row;
        const float* wr = conv_w + (size_t)grow * C_CH;
        float part = gs[lane] * wr[lane] + gs[lane + 32] * wr[lane + 32];
        #pragma unroll
        for (int o = 16; o; o >>= 1) part += __shfl_xor_sync(0xffffffffu, part, o);
        if (lane == 0) {
            float inv = rsqrtf(var[grow] + 1e-5f);
            raw[row] = (part - mean[grow]) * (gamma[grow] * inv) + beta[grow];
        }
    }
    __syncthreads();

    // ---- warp 0: softmax over the 9 taps ----
    if (tid < 32) {
        float val = (tid < KK) ? raw[tid] : -1e30f;
        float m = val;
        #pragma unroll
        for (int o = 16; o; o >>= 1) m = fmaxf(m, __shfl_xor_sync(0xffffffffu, m, o));
        float e = (tid < KK) ? expf(val - m) : 0.f;
        float ssum = e;
        #pragma unroll
        for (int o = 16; o; o >>= 1) ssum += __shfl_xor_sync(0xffffffffu, ssum, o);
        if (tid < KK) wsm[tid] = e / ssum;
    }
    __syncthreads();

    float wt[KK];
    #pragma unroll
    for (int k = 0; k < KK; k++) wt[k] = wsm[k];

    const float4* x4 = reinterpret_cast<const float4*>(x + (size_t)plane * PLANE);
    float4* out4  = reinterpret_cast<float4*>(out  + (size_t)plane * PLANE);
    float4* diff4 = reinterpret_cast<float4*>(diff + (size_t)plane * PLANE);

    int R = R0 + wrp * 8;                  // this warp's 8 output rows: R..R+7

    float acc[3][4];                        // rotating slots, slot = rr % 3
    float ctr[3][4];                        // saved center-row x values (for diff)

    #pragma unroll
    for (int s = 0; s < 10; s++) {          // input row t = R-1+s
        int t  = R - 1 + s;
        int gr = (t < 0) ? 1 : (t > 127 ? 126 : t);     // reflect
        float4 v = x4[gr * 32 + lane];
        float lft = __shfl_up_sync(0xffffffffu, v.w, 1);
        float rgt = __shfl_down_sync(0xffffffffu, v.x, 1);
        if (lane == 0)  lft = v.y;          // xp col 0 = x col 1
        if (lane == 31) rgt = v.z;          // xp col 129 = x col 126
        float sm1[4] = {lft, v.x, v.y, v.z};
        float s00[4] = {v.x, v.y, v.z, v.w};
        float sp1[4] = {v.y, v.z, v.w, rgt};

        // init slot for out row rr = s (weight row 0)
        if (s < 8) {
            int sl = s % 3;
            #pragma unroll
            for (int l = 0; l < 4; l++)
                acc[sl][l] = fmaf(wt[0], sm1[l], fmaf(wt[1], s00[l], wt[2] * sp1[l]));
        }
        // center row for out row rr = s-1 (weight row 1); save x for diff
        if (s >= 1 && s <= 8) {
            int sl = (s - 1) % 3;
            #pragma unroll
            for (int l = 0; l < 4; l++) {
                acc[sl][l] = fmaf(wt[3], sm1[l], fmaf(wt[4], s00[l],
                                  fmaf(wt[5], sp1[l], acc[sl][l])));
                ctr[sl][l] = s00[l];
            }
        }
        // final row for out row rr = s-2 (weight row 2), then emit
        if (s >= 2) {
            int sl = (s - 2) % 3;
            #pragma unroll
            for (int l = 0; l < 4; l++)
                acc[sl][l] = fmaf(wt[6], sm1[l], fmaf(wt[7], s00[l],
                                  fmaf(wt[8], sp1[l], acc[sl][l])));
            int oi = (R + s - 2) * 32 + lane;
            out4[oi]  = make_float4(acc[sl][0], acc[sl][1], acc[sl][2], acc[sl][3]);
            diff4[oi] = make_float4(ctr[sl][0] - acc[sl][0], ctr[sl][1] - acc[sl][1],
                                    ctr[sl][2] - acc[sl][2], ctr[sl][3] - acc[sl][3]);
        }
    }
}

// ---------------------------------------------------------------------------
extern "C" void kernel_launch(void* const* d_in, const int* in_sizes, int n_in,
                              void* d_out, int out_size) {
    const float* x      = (const float*)d_in[0];
    const float* conv_w = (const float*)d_in[1];
    const float* gamma  = (const float*)d_in[2];
    const float* beta   = (const float*)d_in[3];
    const float* mean   = (const float*)d_in[4];
    const float* var    = (const float*)d_in[5];

    float* out  = (float*)d_out;
    float* diff = out + (size_t)NPLANES * PLANE;

    gap_kernel<<<NPLANES * 4, 256>>>(x);
    conv_kernel<<<NPLANES * 2, 256>>>(x, conv_w, gamma, beta, mean, var, out, diff);
}

// round 14
// speedup vs baseline: 3.2222x; 1.0097x over previous
#include <cuda_runtime.h>
#include <cuda_bf16.h>
#include <math.h>

#define N_IMG 8
#define C_CH  64
#define HW    128
#define PLANE (HW*HW)            // 16384
#define NPLANES (N_IMG*C_CH)     // 512
#define KK 9

// gap partial sums: 4 segments per plane
__device__ float g4[NPLANES * 4];

// ---------------------------------------------------------------------------
// Kernel 1: partial global-average-pool. 2048 CTAs, each sums a quarter plane.
// ---------------------------------------------------------------------------
__global__ void gap_kernel(const float* __restrict__ x) {
    int seg = blockIdx.x;                         // plane*4 + q
    const float4* p = reinterpret_cast<const float4*>(x) + (size_t)seg * 1024;
    float s = 0.f;
    #pragma unroll
    for (int k = 0; k < 4; k++) {
        float4 v = p[threadIdx.x + k * 256];
        s += (v.x + v.y) + (v.z + v.w);
    }
    #pragma unroll
    for (int o = 16; o; o >>= 1) s += __shfl_xor_sync(0xffffffffu, s, o);
    __shared__ float ws[8];
    if ((threadIdx.x & 31) == 0) ws[threadIdx.x >> 5] = s;
    __syncthreads();
    if (threadIdx.x == 0) {
        float v = ws[0] + ws[1] + ws[2] + ws[3] + ws[4] + ws[5] + ws[6] + ws[7];
        g4[seg] = v;
    }
}

// ---------------------------------------------------------------------------
// Kernel 2: smem-free warp-shuffle sliding-window conv, CTA per plane.
// Warp = 16 output rows x 128 cols; lane owns 4 cols. Depth-2 load pipeline.
// ---------------------------------------------------------------------------
__global__ __launch_bounds__(256, 4) void conv_kernel(
        const float* __restrict__ x,
        const float* __restrict__ conv_w,
        const float* __restrict__ gamma,
        const float* __restrict__ beta,
        const float* __restrict__ mean,
        const float* __restrict__ var,
        float* __restrict__ out,
        float* __restrict__ diff) {
    __shared__ float gs[C_CH];
    __shared__ float raw[12];
    __shared__ float wsm[12];

    int tid   = threadIdx.x;
    int lane  = tid & 31;
    int wrp   = tid >> 5;
    int plane = blockIdx.x;
    int n     = plane >> 6;
    int ch    = plane & 63;

    // GAP combine for this image's 64 channels
    if (tid < C_CH) {
        const float* g = &g4[(n * C_CH + tid) * 4];
        gs[tid] = (g[0] + g[1] + g[2] + g[3]) * (1.f / (float)PLANE);
    }
    __syncthreads();

    // ---- weight dots distributed over warps: warp w -> rows w, w+8 ----
    for (int row = wrp; row < KK; row += 8) {
        int grow = ch * KK + row;
        const float* wr = conv_w + (size_t)grow * C_CH;
        float part = gs[lane] * wr[lane] + gs[lane + 32] * wr[lane + 32];
        #pragma unroll
        for (int o = 16; o; o >>= 1) part += __shfl_xor_sync(0xffffffffu, part, o);
        if (lane == 0) {
            float inv = rsqrtf(var[grow] + 1e-5f);
            raw[row] = (part - mean[grow]) * (gamma[grow] * inv) + beta[grow];
        }
    }
    __syncthreads();

    // ---- warp 0: softmax over the 9 taps ----
    if (tid < 32) {
        float val = (tid < KK) ? raw[tid] : -1e30f;
        float m = val;
        #pragma unroll
        for (int o = 16; o; o >>= 1) m = fmaxf(m, __shfl_xor_sync(0xffffffffu, m, o));
        float e = (tid < KK) ? expf(val - m) : 0.f;
        float ssum = e;
        #pragma unroll
        for (int o = 16; o; o >>= 1) ssum += __shfl_xor_sync(0xffffffffu, ssum, o);
        if (tid < KK) wsm[tid] = e / ssum;
    }
    __syncthreads();

    float wt[KK];
    #pragma unroll
    for (int k = 0; k < KK; k++) wt[k] = wsm[k];

    const float4* x4 = reinterpret_cast<const float4*>(x + (size_t)plane * PLANE);
    float4* out4  = reinterpret_cast<float4*>(out  + (size_t)plane * PLANE);
    float4* diff4 = reinterpret_cast<float4*>(diff + (size_t)plane * PLANE);

    int R = wrp * 16;                      // this warp's 16 output rows: R..R+15
    const int NS = 18;                     // input rows R-1 .. R+16

    // depth-2 pipelined row loads
    float4 vbuf[2];
    {
        int t0 = R - 1;  int g0 = (t0 < 0) ? 1 : t0;
        vbuf[0] = x4[g0 * 32 + lane];
        vbuf[1] = x4[R * 32 + lane];       // t=R always in range
    }

    float acc[3][4];                        // rotating slots, slot = rr % 3
    float ctr[2][4];                        // center-row x values, slot = rr % 2

    #pragma unroll
    for (int s = 0; s < NS; s++) {          // input row t = R-1+s
        // prefetch row t+2
        float4 v = vbuf[s & 1];
        if (s + 2 < NS) {
            int tp = R + 1 + s;
            int gp = (tp > 127) ? 126 : tp;
            vbuf[s & 1] = x4[gp * 32 + lane];
        }

        float lft = __shfl_up_sync(0xffffffffu, v.w, 1);
        float rgt = __shfl_down_sync(0xffffffffu, v.x, 1);
        if (lane == 0)  lft = v.y;          // xp col 0 = x col 1
        if (lane == 31) rgt = v.z;          // xp col 129 = x col 126
        float sm1[4] = {lft, v.x, v.y, v.z};
        float s00[4] = {v.x, v.y, v.z, v.w};
        float sp1[4] = {v.y, v.z, v.w, rgt};

        // init slot for out row rr = s (weight row 0)
        if (s < 16) {
            int sl = s % 3;
            #pragma unroll
            for (int l = 0; l < 4; l++)
                acc[sl][l] = fmaf(wt[0], sm1[l], fmaf(wt[1], s00[l], wt[2] * sp1[l]));
        }
        // center row for out row rr = s-1 (weight row 1); save x for diff
        if (s >= 1 && s <= 16) {
            int sl = (s - 1) % 3;
            int cs = (s - 1) & 1;
            #pragma unroll
            for (int l = 0; l < 4; l++) {
                acc[sl][l] = fmaf(wt[3], sm1[l], fmaf(wt[4], s00[l],
                                  fmaf(wt[5], sp1[l], acc[sl][l])));
                ctr[cs][l] = s00[l];
            }
        }
        // final row for out row rr = s-2 (weight row 2), then emit
        if (s >= 2) {
            int sl = (s - 2) % 3;
            int cs = (s - 2) & 1;
            #pragma unroll
            for (int l = 0; l < 4; l++)
                acc[sl][l] = fmaf(wt[6], sm1[l], fmaf(wt[7], s00[l],
                                  fmaf(wt[8], sp1[l], acc[sl][l])));
            int oi = (R + s - 2) * 32 + lane;
            out4[oi]  = make_float4(acc[sl][0], acc[sl][1], acc[sl][2], acc[sl][3]);
            diff4[oi] = make_float4(ctr[cs][0] - acc[sl][0], ctr[cs][1] - acc[sl][1],
                                    ctr[cs][2] - acc[sl][2], ctr[cs][3] - acc[sl][3]);
        }
    }
}

// ---------------------------------------------------------------------------
extern "C" void kernel_launch(void* const* d_in, const int* in_sizes, int n_in,
                              void* d_out, int out_size) {
    const float* x      = (const float*)d_in[0];
    const float* conv_w = (const float*)d_in[1];
    const float* gamma  = (const float*)d_in[2];
    const float* beta   = (const float*)d_in[3];
    const float* mean   = (const float*)d_in[4];
    const float* var    = (const float*)d_in[5];

    float* out  = (float*)d_out;
    float* diff = out + (size_t)NPLANES * PLANE;

    gap_kernel<<<NPLANES * 4, 256>>>(x);
    conv_kernel<<<NPLANES, 256>>>(x, conv_w, gamma, beta, mean, var, out, diff);
}